// round 12
// baseline (speedup 1.0000x reference)
#include <cuda_runtime.h>
#include <cstdint>
#include <cstddef>

#define DI __device__ __forceinline__

// ---------------------------------------------------------------------------
// Problem constants
// ---------------------------------------------------------------------------
namespace {
constexpr int B_   = 64;
constexpr int S_   = 2048;
constexpr int F_   = 40;
constexpr int EMB_ = 128;
constexpr int HID_ = 256;
constexpr int G_   = 4 * HID_;                 // 1024 gate rows
constexpr long long MS = (long long)B_ * S_;   // 131072 flattened rows

// Fused recurrence geometry: per layer 8 clusters x 8 CTAs, 8 batches/cluster.
constexpr int CLU  = 8;
constexpr int UPC  = HID_ / CLU;               // 32 units per CTA
constexpr int ROWS = 4 * UPC;                  // 128 gate rows per CTA
constexpr int BPC  = 8;                        // batches per cluster
constexpr int NTHR = 512;
constexpr int NKS  = 4;                        // k-chunks (recurrent part)
constexpr int KC   = HID_ / NKS;               // 64 floats per chunk
constexpr int QN   = KC / 4;                   // 16 x 16B per chunk

// dynamic smem layout (floats)
constexpr int SM_H    = 0;                         // [2][BPC][HID] = 4096
constexpr int SM_RED  = 4096;                      // [NKS][ROWS][BPC] = 4096
constexpr int SM_H0   = 8192;                      // [BPC][HID] = 2048 (L1)
constexpr int SM_WIH  = 10240;                     // [ROWS][260] = 33280 (L1)
constexpr int WPAD    = 260;
constexpr int SM_TOT  = SM_WIH + ROWS * WPAD;      // 43520 floats
constexpr size_t REC_SMEM = (size_t)SM_TOT * 4;    // 174080 B
}

// ---------------------------------------------------------------------------
// Scratch (device globals: no runtime allocation allowed)
// ---------------------------------------------------------------------------
__device__ float g_gx[(size_t)MS * G_];      // 536 MB: gx0 (layer-0 gate preacts)
__device__ float g_hs0[(size_t)MS * HID_];   // 134 MB: layer-0 hidden states
__device__ float g_hs1[(size_t)MS * HID_];   // 134 MB: layer-1 hidden states
__device__ float g_Wc[G_ * F_];              // fused W_ih0 @ W_in
__device__ float g_b0[G_];
__device__ float g_b1[G_];
__device__ unsigned g_flags[CLU * 8];        // [L0 cluster 0..7][rank 0..7]

// ---------------------------------------------------------------------------
// f32x2 helpers (packed dual-FMA; ptxas won't emit from C++)
// ---------------------------------------------------------------------------
DI void ffma2(unsigned long long& acc, unsigned long long a, unsigned long long b) {
    asm("fma.rn.f32x2 %0, %1, %2, %0;" : "+l"(acc) : "l"(a), "l"(b));
}
DI unsigned long long dup2(float x) {
    unsigned long long d;
    unsigned u = __float_as_uint(x);
    asm("mov.b64 %0, {%1, %1};" : "=l"(d) : "r"(u));
    return d;
}
DI float lo2(unsigned long long v) { return __uint_as_float((unsigned)v); }
DI float hi2(unsigned long long v) { return __uint_as_float((unsigned)(v >> 32)); }

DI uint32_t s2u(const void* p) {
    uint32_t a;
    asm("{ .reg .u64 t; cvta.to.shared.u64 t, %1; cvt.u32.u64 %0, t; }"
        : "=r"(a) : "l"(p));
    return a;
}
DI void cluster_sync() {
    asm volatile("barrier.cluster.arrive.aligned;" ::: "memory");
    asm volatile("barrier.cluster.wait.aligned;" ::: "memory");
}
DI void st_cluster_v4(uint32_t local_addr, uint32_t rank,
                      float a, float b, float c, float d) {
    asm volatile(
        "{\n\t.reg .b32 ra;\n\t"
        "mapa.shared::cluster.u32 ra, %0, %1;\n\t"
        "st.shared::cluster.v4.f32 [ra], {%2, %3, %4, %5};\n\t}"
        :: "r"(local_addr), "r"(rank), "f"(a), "f"(b), "f"(c), "f"(d) : "memory");
}
DI unsigned ldcv_u32(const unsigned* p) {
    unsigned v;
    asm volatile("ld.global.cv.u32 %0, [%1];" : "=r"(v) : "l"(p));
    return v;
}

// Fast activations: EX2/RCP approx, saturation-safe at +/-inf.
DI float fex2(float x) { float y; asm("ex2.approx.f32 %0, %1;" : "=f"(y) : "f"(x)); return y; }
DI float frcp(float x) { float y; asm("rcp.approx.f32 %0, %1;" : "=f"(y) : "f"(x)); return y; }
constexpr float LOG2E_ = 1.4426950408889634f;
DI float sigf(float x)     { return frcp(1.f + fex2(-x * LOG2E_)); }
DI float tanhfast(float x) { return 1.f - 2.f * frcp(1.f + fex2(x * (2.f * LOG2E_))); }

// ---------------------------------------------------------------------------
// Prep: Wc = W_ih0 @ W_in, fused biases, flag reset (every replay)
// ---------------------------------------------------------------------------
__global__ void prep_kernel(const float* __restrict__ Wih0, const float* __restrict__ Win,
                            const float* __restrict__ bin,
                            const float* __restrict__ bih0, const float* __restrict__ bhh0,
                            const float* __restrict__ bih1, const float* __restrict__ bhh1) {
    int idx = blockIdx.x * blockDim.x + threadIdx.x;
    if (idx < G_ * F_) {
        int g = idx / F_, f = idx % F_;
        float s = 0.f;
        #pragma unroll 8
        for (int e = 0; e < EMB_; e++) s += Wih0[g * EMB_ + e] * Win[e * F_ + f];
        g_Wc[idx] = s;
    }
    if (idx < G_) {
        float s = bih0[idx] + bhh0[idx];
        #pragma unroll 8
        for (int e = 0; e < EMB_; e++) s += Wih0[idx * EMB_ + e] * bin[e];
        g_b0[idx] = s;
        g_b1[idx] = bih1[idx] + bhh1[idx];
    }
    if (idx < CLU * 8) g_flags[idx] = 0u;   // MUST reset each launch
}

__global__ void noop_kernel() {}

// ---------------------------------------------------------------------------
// GEMM: C[M][N] = A[M][K] @ Bt[N][K] + bias[N]  (used for gx0, K=40)
// ---------------------------------------------------------------------------
__global__ __launch_bounds__(256) void gemm_bias_f32(
    const float* __restrict__ A, const float* __restrict__ Bt,
    const float* __restrict__ bias, float* __restrict__ C, int K, int N) {
    __shared__ float As[8][128];
    __shared__ float Bs[8][128];

    const int tid = threadIdx.x;
    const int m0 = blockIdx.y * 128, n0 = blockIdx.x * 128;
    const int lr = tid >> 1, lq = tid & 1;
    const int ty = tid >> 4, tx = tid & 15;

    unsigned long long acc[4][8];
    #pragma unroll
    for (int i = 0; i < 4; i++)
        #pragma unroll
        for (int j = 0; j < 8; j++) acc[i][j] = 0ull;

    for (int kc = 0; kc < K; kc += 8) {
        float4 av = *(const float4*)(A + (size_t)(m0 + lr) * K + kc + lq * 4);
        float4 bv = *(const float4*)(Bt + (size_t)(n0 + lr) * K + kc + lq * 4);
        __syncthreads();
        As[lq * 4 + 0][lr] = av.x; As[lq * 4 + 1][lr] = av.y;
        As[lq * 4 + 2][lr] = av.z; As[lq * 4 + 3][lr] = av.w;
        Bs[lq * 4 + 0][lr] = bv.x; Bs[lq * 4 + 1][lr] = bv.y;
        Bs[lq * 4 + 2][lr] = bv.z; Bs[lq * 4 + 3][lr] = bv.w;
        __syncthreads();
        #pragma unroll
        for (int k = 0; k < 8; k++) {
            ulonglong2 a01 = *(const ulonglong2*)&As[k][ty * 8];
            ulonglong2 a23 = *(const ulonglong2*)&As[k][ty * 8 + 4];
            float4 bl = *(const float4*)&Bs[k][tx * 8];
            float4 bh = *(const float4*)&Bs[k][tx * 8 + 4];
            unsigned long long ap[4] = { a01.x, a01.y, a23.x, a23.y };
            unsigned long long bd[8] = { dup2(bl.x), dup2(bl.y), dup2(bl.z), dup2(bl.w),
                                         dup2(bh.x), dup2(bh.y), dup2(bh.z), dup2(bh.w) };
            #pragma unroll
            for (int mp = 0; mp < 4; mp++)
                #pragma unroll
                for (int j = 0; j < 8; j++)
                    ffma2(acc[mp][j], ap[mp], bd[j]);
        }
    }

    float bv[8];
    #pragma unroll
    for (int j = 0; j < 8; j++) bv[j] = bias[n0 + tx * 8 + j];

    #pragma unroll
    for (int mp = 0; mp < 4; mp++) {
        int m = m0 + ty * 8 + mp * 2;
        float4 r0a = { lo2(acc[mp][0]) + bv[0], lo2(acc[mp][1]) + bv[1],
                       lo2(acc[mp][2]) + bv[2], lo2(acc[mp][3]) + bv[3] };
        float4 r0b = { lo2(acc[mp][4]) + bv[4], lo2(acc[mp][5]) + bv[5],
                       lo2(acc[mp][6]) + bv[6], lo2(acc[mp][7]) + bv[7] };
        float4 r1a = { hi2(acc[mp][0]) + bv[0], hi2(acc[mp][1]) + bv[1],
                       hi2(acc[mp][2]) + bv[2], hi2(acc[mp][3]) + bv[3] };
        float4 r1b = { hi2(acc[mp][4]) + bv[4], hi2(acc[mp][5]) + bv[5],
                       hi2(acc[mp][6]) + bv[6], hi2(acc[mp][7]) + bv[7] };
        float* c0 = C + (size_t)m * N + n0 + tx * 8;
        float* c1 = c0 + N;
        *(float4*)c0 = r0a;       *(float4*)(c0 + 4) = r0b;
        *(float4*)c1 = r1a;       *(float4*)(c1 + 4) = r1b;
    }
}

// ---------------------------------------------------------------------------
// FUSED 2-layer LSTM recurrence (software pipeline across layers).
// blockIdx < 64: layer 0 (8 clusters x 8 CTAs); >= 64: layer 1 (same).
// L0 publishes h0[t] to gmem + monotonic flag; L1 polls (bounded + backoff),
// folds gx1 into its dot: gates1 = Whh1@h1[t-1] (regs) + Wih1@h0[t] (smem W).
// ---------------------------------------------------------------------------
__global__ void __cluster_dims__(CLU, 1, 1) __launch_bounds__(NTHR, 1)
lstm_fused_kernel(const float* __restrict__ Whh0, const float* __restrict__ Whh1,
                  const float* __restrict__ Wih1, const float* __restrict__ gx) {
    extern __shared__ float sm[];
    float* sH   = sm + SM_H;     // [2][BPC][HID_]
    float* sRed = sm + SM_RED;   // [NKS][ROWS][BPC]
    float* sH0  = sm + SM_H0;    // [BPC][HID_]      (L1 only)
    float* sW   = sm + SM_WIH;   // [ROWS][WPAD]     (L1 only)

    const int tid  = threadIdx.x;
    const bool isL1 = blockIdx.x >= 64;
    const int rank = blockIdx.x & 7;
    const int grp  = (blockIdx.x & 63) >> 3;   // 0..7
    const int r    = tid & 127;
    const int ks   = tid >> 7;
    const int gate = r >> 5;
    const int u    = r & 31;
    const int grow = gate * HID_ + rank * UPC + u;

    // --- recurrent W chunk into registers (layer-specific) ---
    const float* Whh = isL1 ? Whh1 : Whh0;
    unsigned long long w[KC / 2];
    {
        const float4* src = (const float4*)(Whh + (size_t)grow * HID_ + ks * KC);
        #pragma unroll
        for (int i = 0; i < QN; i++) {
            float4 v = src[i];
            ulonglong2 p = *(const ulonglong2*)&v;
            w[2 * i]     = p.x;
            w[2 * i + 1] = p.y;
        }
    }

    // --- L1: stage W_ih1 slice into smem (128 rows x 256, padded 260) ---
    if (isL1) {
        for (int idx = tid; idx < ROWS * (HID_ / 4); idx += NTHR) {
            int rr = idx >> 6, c4 = (idx & 63) * 4;
            int grr = (rr >> 5) * HID_ + rank * UPC + (rr & 31);
            *(float4*)&sW[rr * WPAD + c4] =
                *(const float4*)(Wih1 + (size_t)grr * HID_ + c4);
        }
    }
    for (int i = tid; i < 2 * BPC * HID_; i += NTHR) sH[i] = 0.f;
    __syncthreads();
    cluster_sync();

    // Update-thread state (tid < 256): unit uu, batch bb.
    const int uu = tid >> 3, bb = tid & 7;
    const int batch = grp * BPC + bb;
    float c = 0.f;
    float gxn[4] = {0.f, 0.f, 0.f, 0.f};
    float b1g[4] = {0.f, 0.f, 0.f, 0.f};
    const float* gxbase = gx + (size_t)batch * S_ * G_ + rank * UPC + uu;
    if (tid < 256) {
        if (!isL1) {
            #pragma unroll
            for (int g = 0; g < 4; g++) gxn[g] = __ldg(gxbase + g * HID_);
        } else {
            #pragma unroll
            for (int g = 0; g < 4; g++) b1g[g] = g_b1[g * HID_ + rank * UPC + uu];
        }
    }
    float* hsout = isL1 ? g_hs1 : g_hs0;

    int cur = 0;
    for (int t = 0; t < S_; t++) {
        // L0: prefetch gx[t+1] (clamped — R7 lesson)
        float pf[4];
        if (!isL1 && tid < 256) {
            int tn = (t + 1 < S_) ? (t + 1) : (S_ - 1);
            const float* gp = gxbase + (size_t)tn * G_;
            #pragma unroll
            for (int g = 0; g < 4; g++) pf[g] = __ldg(gp + g * HID_);
        }

        // L1: wait for paired L0 cluster's step t (bounded spin + backoff),
        // then load this CTA's share of the h0 tile.
        float4 h0v;
        if (isL1) {
            const unsigned need = (unsigned)(t + 1);
            unsigned tries = 0;
            for (;;) {
                unsigned v = ldcv_u32(&g_flags[grp * 8 + (tid & 7)]);
                if (__all_sync(0xFFFFFFFFu, v >= need)) break;
                if (++tries > (1u << 22)) break;   // escape hatch: finish wrong, not hang
                __nanosleep(64);
            }
            int lb = tid >> 6, lk = (tid & 63) * 4;
            h0v = *(const float4*)(g_hs0 +
                    ((size_t)(grp * BPC + lb) * S_ + t) * HID_ + lk);
        }

        // ---- recurrent dot over sH[cur]: 4 passes of 2 batches ----
        const float* hp = sH + cur * BPC * HID_;
        float red[8];
        #pragma unroll
        for (int bp = 0; bp < 4; bp++) {
            const ulonglong2* hA = (const ulonglong2*)(hp + (2 * bp + 0) * HID_ + ks * KC);
            const ulonglong2* hB = (const ulonglong2*)(hp + (2 * bp + 1) * HID_ + ks * KC);
            unsigned long long s0 = 0ull, s1 = 0ull, s2 = 0ull, s3 = 0ull;
            #pragma unroll
            for (int q = 0; q < QN; q++) {
                ulonglong2 xA = hA[q];
                ulonglong2 xB = hB[q];
                ffma2(s0, w[2 * q],     xA.x);
                ffma2(s1, w[2 * q + 1], xA.y);
                ffma2(s2, w[2 * q],     xB.x);
                ffma2(s3, w[2 * q + 1], xB.y);
            }
            red[2 * bp + 0] = (lo2(s0) + hi2(s0)) + (lo2(s1) + hi2(s1));
            red[2 * bp + 1] = (lo2(s2) + hi2(s2)) + (lo2(s3) + hi2(s3));
        }

        // ---- L1: input-projection dot over h0 (W from smem), 2x4 batches ----
        if (isL1) {
            int lb = tid >> 6, lk = (tid & 63) * 4;
            *(float4*)&sH0[lb * HID_ + lk] = h0v;
            __syncthreads();
            const float* wrow = &sW[r * WPAD + ks * KC];
            const float* h0b  = &sH0[ks * KC];
            #pragma unroll
            for (int half = 0; half < 2; half++) {
                unsigned long long acc[4] = {0ull, 0ull, 0ull, 0ull};
                #pragma unroll
                for (int q = 0; q < QN; q++) {
                    ulonglong2 wp = *(const ulonglong2*)(wrow + q * 4);
                    #pragma unroll
                    for (int b2 = 0; b2 < 4; b2++) {
                        ulonglong2 x = *(const ulonglong2*)
                            (h0b + (half * 4 + b2) * HID_ + q * 4);
                        ffma2(acc[b2], wp.x, x.x);
                        ffma2(acc[b2], wp.y, x.y);
                    }
                }
                #pragma unroll
                for (int b2 = 0; b2 < 4; b2++)
                    red[half * 4 + b2] += lo2(acc[b2]) + hi2(acc[b2]);
            }
        }

        *(float4*)&sRed[(ks * ROWS + r) * BPC + 0] = *(float4*)&red[0];
        *(float4*)&sRed[(ks * ROWS + r) * BPC + 4] = *(float4*)&red[4];
        __syncthreads();

        // ---- cell update (tid < 256) ----
        if (tid < 256) {
            float gates[4];
            #pragma unroll
            for (int g = 0; g < 4; g++) {
                int rr = g * UPC + uu;
                float s = isL1 ? b1g[g] : gxn[g];
                #pragma unroll
                for (int k2 = 0; k2 < NKS; k2++)
                    s += sRed[(k2 * ROWS + rr) * BPC + bb];
                gates[g] = s;
            }
            if (!isL1) {
                #pragma unroll
                for (int g = 0; g < 4; g++) gxn[g] = pf[g];
            }
            float gi = sigf(gates[0]);
            float gf = sigf(gates[1]);
            float gg = tanhfast(gates[2]);
            float go = sigf(gates[3]);
            c = gf * c + gi * gg;
            float h = go * tanhfast(c);

            // global h store (L0: consumed by L1; L1: consumed by outproj)
            hsout[((size_t)batch * S_ + t) * HID_ + rank * UPC + uu] = h;

            // DSMEM broadcast (packed v4) into next h buffer of all peers
            float h1 = __shfl_down_sync(0xFFFFFFFFu, h, 8);
            float h2 = __shfl_down_sync(0xFFFFFFFFu, h, 16);
            float h3 = __shfl_down_sync(0xFFFFFFFFu, h, 24);
            if ((uu & 3) == 0) {
                uint32_t loc = s2u(sH + (cur ^ 1) * BPC * HID_ + bb * HID_ + rank * UPC + uu);
                #pragma unroll
                for (int p = 0; p < CLU; p++)
                    st_cluster_v4(loc, (uint32_t)p, h, h1, h2, h3);
            }

            if (!isL1) {
                // release: every update thread fences its STG, bar, then flag
                __threadfence();
                asm volatile("bar.sync 1, 256;" ::: "memory");
                if (tid == 0) g_flags[grp * 8 + rank] = (unsigned)(t + 1);
            }
        }
        cluster_sync();
        cur ^= 1;
    }
    cluster_sync();
}

// ---------------------------------------------------------------------------
// Output projection: out[m] = dot(hs1[m], W_out) + b_out  (1 warp per row)
// ---------------------------------------------------------------------------
__global__ __launch_bounds__(256) void outproj_kernel(
    const float* __restrict__ hsbuf, const float* __restrict__ Wout,
    const float* __restrict__ bout, float* __restrict__ out) {
    const long long w = ((long long)blockIdx.x * blockDim.x + threadIdx.x) >> 5;
    const int lane = threadIdx.x & 31;
    if (w >= MS) return;
    const float4* hp = (const float4*)(hsbuf + (size_t)w * HID_);
    const float4* wp = (const float4*)Wout;
    float s = 0.f;
    #pragma unroll
    for (int q = 0; q < 2; q++) {
        float4 h = hp[lane + q * 32];
        float4 ww = wp[lane + q * 32];
        s += h.x * ww.x + h.y * ww.y + h.z * ww.z + h.w * ww.w;
    }
    #pragma unroll
    for (int off = 16; off; off >>= 1) s += __shfl_xor_sync(0xFFFFFFFFu, s, off);
    if (lane == 0) out[w] = s + bout[0];
}

// ---------------------------------------------------------------------------
// Launch
// ---------------------------------------------------------------------------
extern "C" void kernel_launch(void* const* d_in, const int* in_sizes, int n_in,
                              void* d_out, int out_size) {
    const float* in_states = (const float*)d_in[0];
    const float* W_in  = (const float*)d_in[1];
    const float* b_in  = (const float*)d_in[2];
    const float* W_ih0 = (const float*)d_in[3];
    const float* W_hh0 = (const float*)d_in[4];
    const float* b_ih0 = (const float*)d_in[5];
    const float* b_hh0 = (const float*)d_in[6];
    const float* W_ih1 = (const float*)d_in[7];
    const float* W_hh1 = (const float*)d_in[8];
    const float* b_ih1 = (const float*)d_in[9];
    const float* b_hh1 = (const float*)d_in[10];
    const float* W_out = (const float*)d_in[11];
    const float* b_out = (const float*)d_in[12];
    float* out = (float*)d_out;

    float *gx = nullptr, *hs1 = nullptr, *Wc = nullptr, *b0 = nullptr;
    cudaGetSymbolAddress((void**)&gx,  g_gx);
    cudaGetSymbolAddress((void**)&hs1, g_hs1);
    cudaGetSymbolAddress((void**)&Wc,  g_Wc);
    cudaGetSymbolAddress((void**)&b0,  g_b0);

    cudaFuncSetAttribute(lstm_fused_kernel,
                         cudaFuncAttributeMaxDynamicSharedMemorySize, (int)REC_SMEM);

    // 1) fused weights/biases + flag reset (every call — graph replays)
    prep_kernel<<<(G_ * F_ + 255) / 256, 256>>>(W_ih0, W_in, b_in, b_ih0, b_hh0, b_ih1, b_hh1);

    // 2) gx0 = in_states @ Wc^T + b0     (K = 40)
    dim3 ggrid(G_ / 128, (unsigned)(MS / 128));   // (8, 1024)
    gemm_bias_f32<<<ggrid, 256>>>(in_states, Wc, b0, gx, F_, G_);

    // keeps ncu capture slot aligned on the fused kernel
    noop_kernel<<<1, 32>>>();

    // 3) fused 2-layer recurrence (pipelined; gx1 GEMM folded into layer 1)
    lstm_fused_kernel<<<128, NTHR, REC_SMEM>>>(W_hh0, W_hh1, W_ih1, gx);

    // 4) output projection on layer-1 hidden states
    outproj_kernel<<<(unsigned)(MS / 8), 256>>>(hs1, W_out, b_out, out);
}